// round 5
// baseline (speedup 1.0000x reference)
#include <cuda_runtime.h>
#include <cuda_bf16.h>

// Problem constants
static constexpr int KN = 50000;   // nodes
static constexpr int KE = 150000;  // edges
// dims: IN=16, HID=32, LAT=16, EF=8, HE=128

// ---------------- device scratch (static, no allocation) ----------------
__device__ __align__(16) float g_agg[KN * 32];
__device__ __align__(16) float g_h1[KN * 32];
__device__ __align__(16) float g_h2[KN * 32];
__device__ __align__(16) int   g_deg[KN];

// ---------------- f32x2 packed helpers (Blackwell FFMA2) ----------------
__device__ __forceinline__ unsigned long long pack2(float x, float y) {
    unsigned long long r;
    asm("mov.b64 %0, {%1, %2};" : "=l"(r) : "f"(x), "f"(y));
    return r;
}
__device__ __forceinline__ void unpack2(unsigned long long v, float& lo, float& hi) {
    asm("mov.b64 {%0, %1}, %2;" : "=f"(lo), "=f"(hi) : "l"(v));
}
__device__ __forceinline__ unsigned long long ffma2(unsigned long long a,
                                                    unsigned long long b,
                                                    unsigned long long c) {
    unsigned long long d;
    asm("fma.rn.f32x2 %0, %1, %2, %3;" : "=l"(d) : "l"(a), "l"(b), "l"(c));
    return d;
}
__device__ __forceinline__ unsigned long long mul2(unsigned long long a,
                                                   unsigned long long b) {
    unsigned long long d;
    asm("mul.rn.f32x2 %0, %1, %2;" : "=l"(d) : "l"(a), "l"(b));
    return d;
}

// ---------------- zeroing (graph-safe) ----------------
__global__ void zero_f_kernel(float* __restrict__ p, int n) {
    int i = blockIdx.x * 256 + threadIdx.x;
    int i4 = i * 4;
    if (i4 + 3 < n) {
        *(float4*)(p + i4) = make_float4(0.f, 0.f, 0.f, 0.f);
    } else {
        for (int k = i4; k < n; k++) p[k] = 0.f;
    }
}
__global__ void zero_i_kernel(int* __restrict__ p, int n) {
    int i = blockIdx.x * 256 + threadIdx.x;
    if (i < n) p[i] = 0;
}

// ---------------- degree (in-degree by dst), edge_index is int32 ----------------
__global__ void deg_kernel(const int* __restrict__ dst) {
    int i = blockIdx.x * 256 + threadIdx.x;
    if (i < KE) atomicAdd(&g_deg[dst[i]], 1);
}

// ---------------- fused edge kernel, v3 ----------------
// lane = output column, f32x2 lanes = edge pairs (4 pairs = 8 edges / lane group).
// KR=4 k's per chunk: h-pair register cache is hp[4][4] (32 regs) so 3 blocks
// fit per SM (occupancy was the R4 limiter: 2 blocks, issue=45%).
template <int DIN, int DOUT, int TE, int MINB>
__global__ __launch_bounds__(256, MINB)
void edge_kernel(const float* __restrict__ xin,
                 const float* __restrict__ ea,
                 const int* __restrict__ src,
                 const int* __restrict__ dst,
                 const float* __restrict__ w1,
                 const float* __restrict__ b1,
                 const float* __restrict__ w2,
                 const float* __restrict__ b2,
                 float* __restrict__ agg) {
    constexpr int EPW = 8 * (32 / DOUT);   // edges per warp
    constexpr int KSTRIDE = 256 / TE;      // staging stride over k / i
    constexpr int KR = 4;                  // k's per chunk
    constexpr int NCH = 128 / KR;
    constexpr int WCH = KR * DIN * DOUT;   // floats per w2 chunk

    extern __shared__ float sh[];
    float* sw2  = sh;                      // WCH
    float* sh_h = sw2 + WCH;               // 128*TE  (transposed: [k][e])
    float* sx   = sh_h + 128 * TE;         // DIN*TE  (transposed: [i][e])
    float* sea  = sx + DIN * TE;           // TE*8
    float* sw1  = sea + TE * 8;            // 1024
    float* sb1  = sw1 + 1024;              // 128
    float* sb2  = sb1 + 128;               // DIN*DOUT

    const int tid = threadIdx.x;
    const int e0 = blockIdx.x * TE;

    // ---- stage small params + edge_attr tile ----
    for (int i = tid; i < 1024; i += 256) sw1[i] = w1[i];
    if (tid < 128) sb1[tid] = b1[tid];
    for (int i = tid; i < DIN * DOUT; i += 256) sb2[i] = b2[i];
    for (int i = tid; i < TE * 8; i += 256) {
        long long g = (long long)e0 * 8 + i;
        sea[i] = (g < (long long)KE * 8) ? ea[g] : 0.f;
    }
    __syncthreads();

    // ---- edge MLP (h transposed [k][e]) + x staging (transposed [i][e]) ----
    {
        const int me = tid % TE;
        float ear[8];
#pragma unroll
        for (int j = 0; j < 8; j++) ear[j] = sea[me * 8 + j];
        for (int k = tid / TE; k < 128; k += KSTRIDE) {
            float s = sb1[k];
#pragma unroll
            for (int j = 0; j < 8; j++) s = fmaf(ear[j], sw1[j * 128 + k], s);
            sh_h[k * TE + me] = fmaxf(s, 0.f);
        }
        const bool actx = (e0 + me) < KE;
        const int sv = actx ? src[e0 + me] : 0;
        for (int i = tid / TE; i < DIN; i += KSTRIDE) {
            sx[i * TE + me] = actx ? xin[(long long)sv * DIN + i] : 0.f;
        }
    }
    __syncthreads();

    const int lane = tid & 31, warp = tid >> 5;
    const int OLANE = lane % DOUT;
    const int EB = warp * EPW + (lane / DOUT) * 8;  // local edge base, 4 pairs

    unsigned long long msg[4] = {0ull, 0ull, 0ull, 0ull};

    for (int c = 0; c < NCH; c++) {
        // stage w2 chunk (k = KR*c .. KR*c+KR-1)
        {
            const float4* gw = (const float4*)(w2 + c * WCH);
            float4* dw = (float4*)sw2;
#pragma unroll
            for (int i2 = tid; i2 < WCH / 4; i2 += 256) dw[i2] = gw[i2];
        }
        __syncthreads();

        // register-cache h pairs for this chunk (broadcast LDS.64)
        unsigned long long hp[4][KR];
#pragma unroll
        for (int p = 0; p < 4; p++)
#pragma unroll
            for (int kk = 0; kk < KR; kk++)
                hp[p][kk] =
                    *(const unsigned long long*)(sh_h + (c * KR + kk) * TE + EB + 2 * p);

#pragma unroll 2
        for (int i = 0; i < DIN; i++) {
            // unique-per-lane w loads (1 wavefront each), pack interleaved
            unsigned long long acc[4];
            {
                float w0 = sw2[0 * DIN * DOUT + i * DOUT + OLANE];
                unsigned long long wd = pack2(w0, w0);
#pragma unroll
                for (int p = 0; p < 4; p++) acc[p] = mul2(hp[p][0], wd);
            }
#pragma unroll
            for (int kk = 1; kk < KR; kk++) {
                float wv = sw2[kk * DIN * DOUT + i * DOUT + OLANE];
                unsigned long long wd = pack2(wv, wv);
#pragma unroll
                for (int p = 0; p < 4; p++) acc[p] = ffma2(hp[p][kk], wd, acc[p]);
            }
            // fold: msg += x[:,i] * acc_i
#pragma unroll
            for (int p = 0; p < 4; p++) {
                unsigned long long xp =
                    *(const unsigned long long*)(sx + i * TE + EB + 2 * p);
                msg[p] = ffma2(xp, acc[p], msg[p]);
            }
        }
        __syncthreads();
    }

    // ---- b2 term: msg += x @ b2(reshaped DIN x DOUT) ----
#pragma unroll 1
    for (int i = 0; i < DIN; i++) {
        float bv = sb2[i * DOUT + OLANE];
        unsigned long long bd = pack2(bv, bv);
#pragma unroll
        for (int p = 0; p < 4; p++) {
            unsigned long long xp =
                *(const unsigned long long*)(sx + i * TE + EB + 2 * p);
            msg[p] = ffma2(xp, bd, msg[p]);
        }
    }

    // ---- scatter (atomics, one column per lane, 2 edges per pair) ----
#pragma unroll
    for (int p = 0; p < 4; p++) {
        float lo, hi;
        unpack2(msg[p], lo, hi);
        int ge = e0 + EB + 2 * p;
        if (ge < KE)
            atomicAdd(agg + (long long)dst[ge] * DOUT + OLANE, lo);
        if (ge + 1 < KE)
            atomicAdd(agg + (long long)dst[ge + 1] * DOUT + OLANE, hi);
    }
}

// ---------------- node epilogue: mean + root GEMM + bias (+relu) ----------------
template <int DIN, int DOUT, bool MEAN, bool RELU>
__global__ __launch_bounds__(256)
void node_kernel(const float* __restrict__ xin,
                 const float* __restrict__ agg,
                 const float* __restrict__ root,
                 const float* __restrict__ bias,
                 const int* __restrict__ deg,
                 float* __restrict__ out) {
    __shared__ float sroot[DIN * DOUT];
    __shared__ float sbias[DOUT];
    int tid = threadIdx.x;
    for (int i = tid; i < DIN * DOUT; i += 256) sroot[i] = root[i];
    if (tid < DOUT) sbias[tid] = bias[tid];
    __syncthreads();

    int idx = blockIdx.x * 256 + tid;
    if (idx >= KN * DOUT) return;
    int n = idx / DOUT, o = idx % DOUT;

    float v = agg[idx];
    if (MEAN) {
        int d = deg[n];
        v *= 1.f / (d > 0 ? (float)d : 1.f);
    }
    const float* xr = xin + n * DIN;
#pragma unroll
    for (int i = 0; i < DIN; i++) v = fmaf(xr[i], sroot[i * DOUT + o], v);
    v += sbias[o];
    if (RELU) v = fmaxf(v, 0.f);
    out[idx] = v;
}

// ---------------- launch ----------------
static constexpr int smem_bytes3(int DIN, int DOUT, int TE) {
    return (4 * DIN * DOUT + 128 * TE + DIN * TE + TE * 8 + 1024 + 128 +
            DIN * DOUT) * 4;
}

extern "C" void kernel_launch(void* const* d_in, const int* in_sizes, int n_in,
                              void* d_out, int out_size) {
    const float* x = (const float*)d_in[0];
    const int* ei = (const int*)d_in[1];  // int32 (JAX x64-disabled downcast)
    const float* ea = (const float*)d_in[2];
    auto f = [&](int i) { return (const float*)d_in[i]; };
    float* out = (float*)d_out;

    const int* src = ei;
    const int* dstp = ei + KE;

    void *agg_p, *deg_p, *h1_p, *h2_p;
    cudaGetSymbolAddress(&agg_p, g_agg);
    cudaGetSymbolAddress(&deg_p, g_deg);
    cudaGetSymbolAddress(&h1_p, g_h1);
    cudaGetSymbolAddress(&h2_p, g_h2);

    cudaFuncSetAttribute(edge_kernel<16, 32, 64, 3>,
                         cudaFuncAttributeMaxDynamicSharedMemorySize,
                         smem_bytes3(16, 32, 64));
    cudaFuncSetAttribute(edge_kernel<32, 32, 64, 3>,
                         cudaFuncAttributeMaxDynamicSharedMemorySize,
                         smem_bytes3(32, 32, 64));
    cudaFuncSetAttribute(edge_kernel<32, 16, 128, 2>,
                         cudaFuncAttributeMaxDynamicSharedMemorySize,
                         smem_bytes3(32, 16, 128));

    const int EB64 = (KE + 63) / 64;
    const int EB128 = (KE + 127) / 128;
    const int ZB32 = (KN * 32 / 4 + 255) / 256;
    const int ZB16 = (KN * 16 / 4 + 255) / 256;

    // degree histogram (shared by conv1/conv2 mean)
    zero_i_kernel<<<(KN + 255) / 256, 256>>>((int*)deg_p, KN);
    deg_kernel<<<(KE + 255) / 256, 256>>>(dstp);

    // conv1: IN=16 -> HID=32, mean, relu
    zero_f_kernel<<<ZB32, 256>>>((float*)agg_p, KN * 32);
    edge_kernel<16, 32, 64, 3><<<EB64, 256, smem_bytes3(16, 32, 64)>>>(
        x, ea, src, dstp, f(3), f(4), f(5), f(6), (float*)agg_p);
    node_kernel<16, 32, true, true><<<(KN * 32 + 255) / 256, 256>>>(
        x, (const float*)agg_p, f(7), f(8), (const int*)deg_p, (float*)h1_p);

    // conv2: 32 -> 32, mean, relu
    zero_f_kernel<<<ZB32, 256>>>((float*)agg_p, KN * 32);
    edge_kernel<32, 32, 64, 3><<<EB64, 256, smem_bytes3(32, 32, 64)>>>(
        (const float*)h1_p, ea, src, dstp, f(9), f(10), f(11), f(12),
        (float*)agg_p);
    node_kernel<32, 32, true, true><<<(KN * 32 + 255) / 256, 256>>>(
        (const float*)h1_p, (const float*)agg_p, f(13), f(14), (const int*)deg_p,
        (float*)h2_p);

    // mu: 32 -> 16, sum, no relu  -> out[0 : N*16]
    zero_f_kernel<<<ZB16, 256>>>((float*)agg_p, KN * 16);
    edge_kernel<32, 16, 128, 2><<<EB128, 256, smem_bytes3(32, 16, 128)>>>(
        (const float*)h2_p, ea, src, dstp, f(15), f(16), f(17), f(18),
        (float*)agg_p);
    node_kernel<32, 16, false, false><<<(KN * 16 + 255) / 256, 256>>>(
        (const float*)h2_p, (const float*)agg_p, f(19), f(20), (const int*)deg_p,
        out);

    // logvar: 32 -> 16, sum, no relu -> out[N*16 : 2*N*16]
    zero_f_kernel<<<ZB16, 256>>>((float*)agg_p, KN * 16);
    edge_kernel<32, 16, 128, 2><<<EB128, 256, smem_bytes3(32, 16, 128)>>>(
        (const float*)h2_p, ea, src, dstp, f(21), f(22), f(23), f(24),
        (float*)agg_p);
    node_kernel<32, 16, false, false><<<(KN * 16 + 255) / 256, 256>>>(
        (const float*)h2_p, (const float*)agg_p, f(25), f(26), (const int*)deg_p,
        out + KN * 16);
}

// round 6
// speedup vs baseline: 1.0836x; 1.0836x over previous
#include <cuda_runtime.h>
#include <cuda_bf16.h>
#include <cstdint>

// Problem constants
static constexpr int KN = 50000;   // nodes
static constexpr int KE = 150000;  // edges
// dims: IN=16, HID=32, LAT=16, EF=8, HE=128

// ---------------- device scratch (static, no allocation) ----------------
__device__ __align__(16) float g_agg[KN * 32];
__device__ __align__(16) float g_h1[KN * 32];
__device__ __align__(16) float g_h2[KN * 32];
__device__ __align__(16) int   g_deg[KN];

// ---------------- f32x2 packed helpers (Blackwell FFMA2) ----------------
__device__ __forceinline__ unsigned long long pack2(float x, float y) {
    unsigned long long r;
    asm("mov.b64 %0, {%1, %2};" : "=l"(r) : "f"(x), "f"(y));
    return r;
}
__device__ __forceinline__ void unpack2(unsigned long long v, float& lo, float& hi) {
    asm("mov.b64 {%0, %1}, %2;" : "=f"(lo), "=f"(hi) : "l"(v));
}
__device__ __forceinline__ unsigned long long ffma2(unsigned long long a,
                                                    unsigned long long b,
                                                    unsigned long long c) {
    unsigned long long d;
    asm("fma.rn.f32x2 %0, %1, %2, %3;" : "=l"(d) : "l"(a), "l"(b), "l"(c));
    return d;
}
__device__ __forceinline__ unsigned long long mul2(unsigned long long a,
                                                   unsigned long long b) {
    unsigned long long d;
    asm("mul.rn.f32x2 %0, %1, %2;" : "=l"(d) : "l"(a), "l"(b));
    return d;
}

// ---------------- cp.async helpers ----------------
__device__ __forceinline__ void cp_async16(uint32_t saddr, const void* gptr) {
    asm volatile("cp.async.cg.shared.global [%0], [%1], 16;" ::"r"(saddr),
                 "l"(gptr));
}
__device__ __forceinline__ void cp_commit() {
    asm volatile("cp.async.commit_group;");
}
__device__ __forceinline__ void cp_wait1() {
    asm volatile("cp.async.wait_group 1;");
}
__device__ __forceinline__ void cp_wait0() {
    asm volatile("cp.async.wait_group 0;");
}

// ---------------- zeroing (graph-safe) ----------------
__global__ void zero_f_kernel(float* __restrict__ p, int n) {
    int i = blockIdx.x * 256 + threadIdx.x;
    int i4 = i * 4;
    if (i4 + 3 < n) {
        *(float4*)(p + i4) = make_float4(0.f, 0.f, 0.f, 0.f);
    } else {
        for (int k = i4; k < n; k++) p[k] = 0.f;
    }
}
__global__ void zero_i_kernel(int* __restrict__ p, int n) {
    int i = blockIdx.x * 256 + threadIdx.x;
    if (i < n) p[i] = 0;
}

// ---------------- degree (in-degree by dst), edge_index is int32 ----------------
__global__ void deg_kernel(const int* __restrict__ dst) {
    int i = blockIdx.x * 256 + threadIdx.x;
    if (i < KE) atomicAdd(&g_deg[dst[i]], 1);
}

// ---------------- fused edge kernel, v4 ----------------
// R4 structure (KR=8, best config) + 2-stage cp.async double-buffering of the
// w2 chunks so chunk-load latency is hidden behind compute (R4/R5 showed the
// exposed load tail at each chunk barrier was the real limiter, not occupancy).
// Prologue scratch (ea/w1/b1) overlays the w2 buffers (filled only later).
template <int DIN, int DOUT, int TE>
__global__ __launch_bounds__(256, 2)
void edge_kernel(const float* __restrict__ xin,
                 const float* __restrict__ ea,
                 const int* __restrict__ src,
                 const int* __restrict__ dst,
                 const float* __restrict__ w1,
                 const float* __restrict__ b1,
                 const float* __restrict__ w2,
                 const float* __restrict__ b2,
                 float* __restrict__ agg) {
    constexpr int EPW = 8 * (32 / DOUT);   // edges per warp
    constexpr int KSTRIDE = 256 / TE;      // staging stride over k / i
    constexpr int KR = 8;                  // k's per chunk
    constexpr int NCH = 128 / KR;          // 16 chunks
    constexpr int WCH = KR * DIN * DOUT;   // floats per w2 chunk
    constexpr int F4PT = WCH / 4 / 256;    // float4s per thread per chunk

    extern __shared__ float sh[];
    float* sw2[2] = {sh, sh + WCH};        // double-buffered w2 chunks
    float* sh_h = sh + 2 * WCH;            // 128*TE  (transposed: [k][e])
    float* sx   = sh_h + 128 * TE;         // DIN*TE  (transposed: [i][e])
    float* sb2  = sx + DIN * TE;           // DIN*DOUT
    // prologue-only overlays inside the (not-yet-used) w2 buffers:
    float* sea = sh;                       // TE*8
    float* sw1 = sh + TE * 8;              // 1024
    float* sb1 = sw1 + 1024;               // 128   (TE*8+1152 <= 2*WCH always)

    const int tid = threadIdx.x;
    const int e0 = blockIdx.x * TE;

    // ---- stage prologue data ----
    for (int i = tid; i < 1024; i += 256) sw1[i] = w1[i];
    if (tid < 128) sb1[tid] = b1[tid];
    for (int i = tid; i < DIN * DOUT; i += 256) sb2[i] = b2[i];
    for (int i = tid; i < TE * 8; i += 256) {
        long long g = (long long)e0 * 8 + i;
        sea[i] = (g < (long long)KE * 8) ? ea[g] : 0.f;
    }
    __syncthreads();

    // ---- edge MLP (h transposed [k][e]) + x staging (transposed [i][e]) ----
    {
        const int me = tid % TE;
        float ear[8];
#pragma unroll
        for (int j = 0; j < 8; j++) ear[j] = sea[me * 8 + j];
        for (int k = tid / TE; k < 128; k += KSTRIDE) {
            float s = sb1[k];
#pragma unroll
            for (int j = 0; j < 8; j++) s = fmaf(ear[j], sw1[j * 128 + k], s);
            sh_h[k * TE + me] = fmaxf(s, 0.f);
        }
        const bool actx = (e0 + me) < KE;
        const int sv = actx ? src[e0 + me] : 0;
        for (int i = tid / TE; i < DIN; i += KSTRIDE) {
            sx[i * TE + me] = actx ? xin[(long long)sv * DIN + i] : 0.f;
        }
    }
    __syncthreads();   // prologue overlays dead; sw2 buffers free now

    // ---- kick cp.async for chunks 0 and 1 ----
    {
        uint32_t s0 = (uint32_t)__cvta_generic_to_shared(sw2[0]) + tid * 16;
        uint32_t s1 = (uint32_t)__cvta_generic_to_shared(sw2[1]) + tid * 16;
#pragma unroll
        for (int i2 = 0; i2 < F4PT; i2++)
            cp_async16(s0 + i2 * 4096, w2 + (tid + i2 * 256) * 4);
        cp_commit();
#pragma unroll
        for (int i2 = 0; i2 < F4PT; i2++)
            cp_async16(s1 + i2 * 4096, w2 + WCH + (tid + i2 * 256) * 4);
        cp_commit();
    }

    const int lane = tid & 31, warp = tid >> 5;
    const int OLANE = lane % DOUT;
    const int EB = warp * EPW + (lane / DOUT) * 8;  // local edge base, 4 pairs

    unsigned long long msg[4] = {0ull, 0ull, 0ull, 0ull};

    for (int c = 0; c < NCH; c++) {
        if (c + 1 < NCH) cp_wait1(); else cp_wait0();
        __syncthreads();   // chunk c visible to all; all done with buf from c-2

        const float* wbuf = sw2[c & 1];

        // register-cache h pairs for this chunk (broadcast LDS.64)
        unsigned long long hp[4][KR];
#pragma unroll
        for (int p = 0; p < 4; p++)
#pragma unroll
            for (int kk = 0; kk < KR; kk++)
                hp[p][kk] = *(const unsigned long long*)(sh_h +
                                (c * KR + kk) * TE + EB + 2 * p);

#pragma unroll 2
        for (int i = 0; i < DIN; i++) {
            unsigned long long acc[4];
            {
                float w0 = wbuf[0 * DIN * DOUT + i * DOUT + OLANE];
                unsigned long long wd = pack2(w0, w0);
#pragma unroll
                for (int p = 0; p < 4; p++) acc[p] = mul2(hp[p][0], wd);
            }
#pragma unroll
            for (int kk = 1; kk < KR; kk++) {
                float wv = wbuf[kk * DIN * DOUT + i * DOUT + OLANE];
                unsigned long long wd = pack2(wv, wv);
#pragma unroll
                for (int p = 0; p < 4; p++) acc[p] = ffma2(hp[p][kk], wd, acc[p]);
            }
#pragma unroll
            for (int p = 0; p < 4; p++) {
                unsigned long long xp =
                    *(const unsigned long long*)(sx + i * TE + EB + 2 * p);
                msg[p] = ffma2(xp, acc[p], msg[p]);
            }
        }
        __syncthreads();   // everyone finished with buf[c&1]

        if (c + 2 < NCH) {  // prefetch chunk c+2 into the buffer just freed
            uint32_t sb = (uint32_t)__cvta_generic_to_shared(sw2[c & 1]) + tid * 16;
            const float* gsrc = w2 + (long long)(c + 2) * WCH;
#pragma unroll
            for (int i2 = 0; i2 < F4PT; i2++)
                cp_async16(sb + i2 * 4096, gsrc + (tid + i2 * 256) * 4);
            cp_commit();
        } else {
            cp_commit();    // keep group accounting uniform
        }
    }

    // ---- b2 term: msg += x @ b2(reshaped DIN x DOUT) ----
#pragma unroll 1
    for (int i = 0; i < DIN; i++) {
        float bv = sb2[i * DOUT + OLANE];
        unsigned long long bd = pack2(bv, bv);
#pragma unroll
        for (int p = 0; p < 4; p++) {
            unsigned long long xp =
                *(const unsigned long long*)(sx + i * TE + EB + 2 * p);
            msg[p] = ffma2(xp, bd, msg[p]);
        }
    }

    // ---- scatter (atomics, one column per lane, 2 edges per pair) ----
#pragma unroll
    for (int p = 0; p < 4; p++) {
        float lo, hi;
        unpack2(msg[p], lo, hi);
        int ge = e0 + EB + 2 * p;
        if (ge < KE)
            atomicAdd(agg + (long long)dst[ge] * DOUT + OLANE, lo);
        if (ge + 1 < KE)
            atomicAdd(agg + (long long)dst[ge + 1] * DOUT + OLANE, hi);
    }
}

// ---------------- node epilogue: mean + root GEMM + bias (+relu) ----------------
template <int DIN, int DOUT, bool MEAN, bool RELU>
__global__ __launch_bounds__(256)
void node_kernel(const float* __restrict__ xin,
                 const float* __restrict__ agg,
                 const float* __restrict__ root,
                 const float* __restrict__ bias,
                 const int* __restrict__ deg,
                 float* __restrict__ out) {
    __shared__ float sroot[DIN * DOUT];
    __shared__ float sbias[DOUT];
    int tid = threadIdx.x;
    for (int i = tid; i < DIN * DOUT; i += 256) sroot[i] = root[i];
    if (tid < DOUT) sbias[tid] = bias[tid];
    __syncthreads();

    int idx = blockIdx.x * 256 + tid;
    if (idx >= KN * DOUT) return;
    int n = idx / DOUT, o = idx % DOUT;

    float v = agg[idx];
    if (MEAN) {
        int d = deg[n];
        v *= 1.f / (d > 0 ? (float)d : 1.f);
    }
    const float* xr = xin + n * DIN;
#pragma unroll
    for (int i = 0; i < DIN; i++) v = fmaf(xr[i], sroot[i * DOUT + o], v);
    v += sbias[o];
    if (RELU) v = fmaxf(v, 0.f);
    out[idx] = v;
}

// ---------------- launch ----------------
static constexpr int smem_bytes4(int DIN, int DOUT, int TE) {
    return (2 * 8 * DIN * DOUT + 128 * TE + DIN * TE + DIN * DOUT) * 4;
}

extern "C" void kernel_launch(void* const* d_in, const int* in_sizes, int n_in,
                              void* d_out, int out_size) {
    const float* x = (const float*)d_in[0];
    const int* ei = (const int*)d_in[1];  // int32 (JAX x64-disabled downcast)
    const float* ea = (const float*)d_in[2];
    auto f = [&](int i) { return (const float*)d_in[i]; };
    float* out = (float*)d_out;

    const int* src = ei;
    const int* dstp = ei + KE;

    void *agg_p, *deg_p, *h1_p, *h2_p;
    cudaGetSymbolAddress(&agg_p, g_agg);
    cudaGetSymbolAddress(&deg_p, g_deg);
    cudaGetSymbolAddress(&h1_p, g_h1);
    cudaGetSymbolAddress(&h2_p, g_h2);

    cudaFuncSetAttribute(edge_kernel<16, 32, 64>,
                         cudaFuncAttributeMaxDynamicSharedMemorySize,
                         smem_bytes4(16, 32, 64));
    cudaFuncSetAttribute(edge_kernel<32, 32, 64>,
                         cudaFuncAttributeMaxDynamicSharedMemorySize,
                         smem_bytes4(32, 32, 64));
    cudaFuncSetAttribute(edge_kernel<32, 16, 128>,
                         cudaFuncAttributeMaxDynamicSharedMemorySize,
                         smem_bytes4(32, 16, 128));

    const int EB64 = (KE + 63) / 64;
    const int EB128 = (KE + 127) / 128;
    const int ZB32 = (KN * 32 / 4 + 255) / 256;
    const int ZB16 = (KN * 16 / 4 + 255) / 256;

    // degree histogram (shared by conv1/conv2 mean)
    zero_i_kernel<<<(KN + 255) / 256, 256>>>((int*)deg_p, KN);
    deg_kernel<<<(KE + 255) / 256, 256>>>(dstp);

    // conv1: IN=16 -> HID=32, mean, relu
    zero_f_kernel<<<ZB32, 256>>>((float*)agg_p, KN * 32);
    edge_kernel<16, 32, 64><<<EB64, 256, smem_bytes4(16, 32, 64)>>>(
        x, ea, src, dstp, f(3), f(4), f(5), f(6), (float*)agg_p);
    node_kernel<16, 32, true, true><<<(KN * 32 + 255) / 256, 256>>>(
        x, (const float*)agg_p, f(7), f(8), (const int*)deg_p, (float*)h1_p);

    // conv2: 32 -> 32, mean, relu
    zero_f_kernel<<<ZB32, 256>>>((float*)agg_p, KN * 32);
    edge_kernel<32, 32, 64><<<EB64, 256, smem_bytes4(32, 32, 64)>>>(
        (const float*)h1_p, ea, src, dstp, f(9), f(10), f(11), f(12),
        (float*)agg_p);
    node_kernel<32, 32, true, true><<<(KN * 32 + 255) / 256, 256>>>(
        (const float*)h1_p, (const float*)agg_p, f(13), f(14), (const int*)deg_p,
        (float*)h2_p);

    // mu: 32 -> 16, sum, no relu  -> out[0 : N*16]
    zero_f_kernel<<<ZB16, 256>>>((float*)agg_p, KN * 16);
    edge_kernel<32, 16, 128><<<EB128, 256, smem_bytes4(32, 16, 128)>>>(
        (const float*)h2_p, ea, src, dstp, f(15), f(16), f(17), f(18),
        (float*)agg_p);
    node_kernel<32, 16, false, false><<<(KN * 16 + 255) / 256, 256>>>(
        (const float*)h2_p, (const float*)agg_p, f(19), f(20), (const int*)deg_p,
        out);

    // logvar: 32 -> 16, sum, no relu -> out[N*16 : 2*N*16]
    zero_f_kernel<<<ZB16, 256>>>((float*)agg_p, KN * 16);
    edge_kernel<32, 16, 128><<<EB128, 256, smem_bytes4(32, 16, 128)>>>(
        (const float*)h2_p, ea, src, dstp, f(21), f(22), f(23), f(24),
        (float*)agg_p);
    node_kernel<32, 16, false, false><<<(KN * 16 + 255) / 256, 256>>>(
        (const float*)h2_p, (const float*)agg_p, f(25), f(26), (const int*)deg_p,
        out + KN * 16);
}

// round 8
// speedup vs baseline: 2.4306x; 2.2431x over previous
#include <cuda_runtime.h>
#include <cuda_bf16.h>
#include <cstdint>

// Problem constants
static constexpr int KN = 50000;   // nodes
static constexpr int KE = 150000;  // edges
// dims: IN=16, HID=32, LAT=16, EF=8, HE=128
static constexpr int PK = 136;     // bf16 pitch for [n][k] / [e][k] tiles

// ---------------- device scratch (static, no allocation) ----------------
__device__ __align__(16) float g_agg[KN * 32];
__device__ __align__(16) float g_h1[KN * 32];
__device__ __align__(16) float g_h2[KN * 32];
__device__ __align__(16) float g_t[KN * 32];   // per-node x@b2 term
__device__ __align__(16) int   g_deg[KN];
// prepped w2: [n][PK] bf16, hi image then lo image
__device__ __align__(16) uint8_t g_w2t_c1[512 * PK * 2 * 2];
__device__ __align__(16) uint8_t g_w2t_c2[1024 * PK * 2 * 2];
__device__ __align__(16) uint8_t g_w2t_mu[512 * PK * 2 * 2];
__device__ __align__(16) uint8_t g_w2t_lv[512 * PK * 2 * 2];

// ---------------- helpers ----------------
__device__ __forceinline__ void cp_async16(uint32_t saddr, const void* gptr) {
    asm volatile("cp.async.cg.shared.global [%0], [%1], 16;" ::"r"(saddr), "l"(gptr));
}
__device__ __forceinline__ void cp_commit() { asm volatile("cp.async.commit_group;"); }
__device__ __forceinline__ void cp_wait1() { asm volatile("cp.async.wait_group 1;"); }
__device__ __forceinline__ void cp_wait0() { asm volatile("cp.async.wait_group 0;"); }

__device__ __forceinline__ void mma16816(float* d, const uint32_t* a,
                                         const uint32_t* b) {
    asm volatile(
        "mma.sync.aligned.m16n8k16.row.col.f32.bf16.bf16.f32 "
        "{%0,%1,%2,%3}, {%4,%5,%6,%7}, {%8,%9}, {%0,%1,%2,%3};"
        : "+f"(d[0]), "+f"(d[1]), "+f"(d[2]), "+f"(d[3])
        : "r"(a[0]), "r"(a[1]), "r"(a[2]), "r"(a[3]), "r"(b[0]), "r"(b[1]));
}

// ---------------- zeroing / degree ----------------
__global__ void zero_f_kernel(float* __restrict__ p, int n) {
    int i = blockIdx.x * 256 + threadIdx.x;
    int i4 = i * 4;
    if (i4 + 3 < n) *(float4*)(p + i4) = make_float4(0.f, 0.f, 0.f, 0.f);
    else for (int k = i4; k < n; k++) p[k] = 0.f;
}
__global__ void zero_i_kernel(int* __restrict__ p, int n) {
    int i = blockIdx.x * 256 + threadIdx.x;
    if (i < n) p[i] = 0;
}
__global__ void deg_kernel(const int* __restrict__ dst) {
    int i = blockIdx.x * 256 + threadIdx.x;
    if (i < KE) atomicAdd(&g_deg[dst[i]], 1);
}

// ---------------- w2 prep: transpose + bf16 hi/lo split ----------------
// input w2: [128 k][dd n] f32; output: hi image [n][PK] bf16, then lo image.
__global__ void prep_w2_kernel(const float* __restrict__ w2, int dd,
                               uint8_t* __restrict__ outb) {
    int idx = blockIdx.x * 256 + threadIdx.x;
    if (idx >= dd * 128) return;
    int n = idx >> 7, k = idx & 127;
    float v = w2[k * dd + n];
    __nv_bfloat16 hi = __float2bfloat16(v);
    __nv_bfloat16 lo = __float2bfloat16(v - __bfloat162float(hi));
    int off = (n * PK + k) * 2;
    int loq = dd * PK * 2;
    *(__nv_bfloat16*)(outb + off) = hi;
    *(__nv_bfloat16*)(outb + loq + off) = lo;
}

// ---------------- per-node x@b2 ----------------
template <int DIN, int DOUT>
__global__ __launch_bounds__(256)
void xb2_kernel(const float* __restrict__ xin, const float* __restrict__ b2,
                float* __restrict__ t) {
    __shared__ float sb[DIN * DOUT];
    int tid = threadIdx.x;
    for (int i = tid; i < DIN * DOUT; i += 256) sb[i] = b2[i];
    __syncthreads();
    int idx = blockIdx.x * 256 + tid;
    if (idx >= KN * DOUT) return;
    int n = idx / DOUT, o = idx % DOUT;
    float s = 0.f;
#pragma unroll
    for (int i = 0; i < DIN; i++) s = fmaf(xin[n * DIN + i], sb[i * DOUT + o], s);
    t[idx] = s;
}

// ---------------- HMMA edge kernel ----------------
// Tile = 128 edges, 256 threads (8 warps, warp w -> edge rows [16w,16w+16)).
// A = h split bf16 [128e x 128k]; B = prepped w2t [n][k] chunks of 64 cols.
// 3-GEMM split (hh + hl + lh); D folded with x per chunk; atomics per (e,o).
template <int DIN, int DOUT>
__global__ __launch_bounds__(256, 1)
void edge_mma_kernel(const float* __restrict__ xin,
                     const float* __restrict__ ea,
                     const int* __restrict__ src,
                     const int* __restrict__ dst,
                     const float* __restrict__ w1,
                     const float* __restrict__ b1,
                     const uint8_t* __restrict__ w2t,
                     const float* __restrict__ tnode,
                     float* __restrict__ agg) {
    constexpr int DD = DIN * DOUT;
    constexpr int NCH = DD / 64;            // 64-col chunks
    constexpr int NSL = DOUT / 4;           // msg slots per thread per edge
    constexpr int ASZ = 128 * PK * 2;       // 34816 B per A image
    constexpr int BHALF = 64 * PK * 2;      // 17408 B per split per chunk
    constexpr int BSZ = 2 * BHALF;          // hi+lo per chunk buffer
    const int LOQ = DD * PK * 2;            // lo-image offset in w2t

    extern __shared__ char shb[];
    uint8_t* A_hi = (uint8_t*)shb;          // [e][k] bf16
    uint8_t* A_lo = A_hi + ASZ;
    uint8_t* Bbuf0 = A_lo + ASZ;            // double-buffered B chunks
    uint8_t* Bbuf1 = Bbuf0 + BSZ;
    float* sx = (float*)(Bbuf1 + BSZ);      // [i][e] f32
    // prologue overlays (dead before first B prefetch)
    float* sea = (float*)Bbuf0;             // 128*8
    float* sw1 = sea + 1024;                // 1024
    float* sb1 = sw1 + 1024;                // 128

    const int tid = threadIdx.x;
    const int lane = tid & 31, warp = tid >> 5;
    const int e0 = blockIdx.x * 128;

    // ---- prologue staging ----
    for (int i = tid; i < 1024; i += 256) sw1[i] = w1[i];
    if (tid < 128) sb1[tid] = b1[tid];
    for (int i = tid; i < 1024; i += 256) {
        long long g = (long long)e0 * 8 + i;
        sea[i] = (g < (long long)KE * 8) ? ea[g] : 0.f;
    }
    __syncthreads();

    // ---- x staging ----
    for (int idx = tid; idx < DIN * 128; idx += 256) {
        int e = idx & 127, i = idx >> 7;
        bool a = (e0 + e) < KE;
        int sv = a ? src[e0 + e] : 0;
        sx[idx] = a ? xin[(long long)sv * DIN + i] : 0.f;
    }
    // ---- edge MLP -> split bf16 A images ----
    for (int idx = tid; idx < 16384; idx += 256) {
        int e = idx >> 7, k = idx & 127;
        float s = sb1[k];
#pragma unroll
        for (int j = 0; j < 8; j++) s = fmaf(sea[e * 8 + j], sw1[j * 128 + k], s);
        s = fmaxf(s, 0.f);
        __nv_bfloat16 hi = __float2bfloat16(s);
        __nv_bfloat16 lo = __float2bfloat16(s - __bfloat162float(hi));
        int off = (e * PK + k) * 2;
        *(__nv_bfloat16*)(A_hi + off) = hi;
        *(__nv_bfloat16*)(A_lo + off) = lo;
    }
    __syncthreads();   // overlays dead; A/sx ready; B buffers free

    // ---- prefetch B chunk 0 ----
    {
        uint32_t s0 = (uint32_t)__cvta_generic_to_shared(Bbuf0);
        for (int j = tid; j < BHALF / 16; j += 256)
            cp_async16(s0 + j * 16, w2t + j * 16);
        for (int j = tid; j < BHALF / 16; j += 256)
            cp_async16(s0 + BHALF + j * 16, w2t + LOQ + j * 16);
        cp_commit();
    }

    const int r0 = warp * 16;
    const int gr = lane >> 2;          // 0..7
    const int c2 = (lane & 3) * 2;     // 0,2,4,6
    const int rA = r0 + gr;

    float msg[2][NSL];
#pragma unroll
    for (int p = 0; p < 2; p++)
#pragma unroll
        for (int s = 0; s < NSL; s++) msg[p][s] = 0.f;

    for (int nc = 0; nc < NCH; nc++) {
        // prefetch next chunk into the other buffer
        if (nc + 1 < NCH) {
            uint8_t* nb = (nc & 1) ? Bbuf0 : Bbuf1;
            uint32_t sb = (uint32_t)__cvta_generic_to_shared(nb);
            const uint8_t* gh = w2t + (long long)(nc + 1) * BHALF;
            const uint8_t* gl = w2t + LOQ + (long long)(nc + 1) * BHALF;
            for (int j = tid; j < BHALF / 16; j += 256)
                cp_async16(sb + j * 16, gh + j * 16);
            for (int j = tid; j < BHALF / 16; j += 256)
                cp_async16(sb + BHALF + j * 16, gl + j * 16);
            cp_commit();
            cp_wait1();
        } else {
            cp_wait0();
        }
        __syncthreads();   // chunk nc resident for all warps

        const uint8_t* Bc = (nc & 1) ? Bbuf1 : Bbuf0;
        const uint8_t* Bh = Bc;
        const uint8_t* Bl = Bc + BHALF;

        float d[8][4];
#pragma unroll
        for (int n8 = 0; n8 < 8; n8++)
#pragma unroll
            for (int q = 0; q < 4; q++) d[n8][q] = 0.f;

#pragma unroll
        for (int k16 = 0; k16 < 8; k16++) {
            const int kb = k16 * 16;
            uint32_t ah[4], al[4];
            ah[0] = *(const uint32_t*)(A_hi + (rA * PK + kb + c2) * 2);
            ah[1] = *(const uint32_t*)(A_hi + ((rA + 8) * PK + kb + c2) * 2);
            ah[2] = *(const uint32_t*)(A_hi + (rA * PK + kb + c2 + 8) * 2);
            ah[3] = *(const uint32_t*)(A_hi + ((rA + 8) * PK + kb + c2 + 8) * 2);
            al[0] = *(const uint32_t*)(A_lo + (rA * PK + kb + c2) * 2);
            al[1] = *(const uint32_t*)(A_lo + ((rA + 8) * PK + kb + c2) * 2);
            al[2] = *(const uint32_t*)(A_lo + (rA * PK + kb + c2 + 8) * 2);
            al[3] = *(const uint32_t*)(A_lo + ((rA + 8) * PK + kb + c2 + 8) * 2);
#pragma unroll
            for (int n8 = 0; n8 < 8; n8++) {
                const int gn = n8 * 8 + gr;
                uint32_t bh[2], bl[2];
                bh[0] = *(const uint32_t*)(Bh + (gn * PK + kb + c2) * 2);
                bh[1] = *(const uint32_t*)(Bh + (gn * PK + kb + c2 + 8) * 2);
                bl[0] = *(const uint32_t*)(Bl + (gn * PK + kb + c2) * 2);
                bl[1] = *(const uint32_t*)(Bl + (gn * PK + kb + c2 + 8) * 2);
                mma16816(d[n8], ah, bh);
                mma16816(d[n8], ah, bl);
                mma16816(d[n8], al, bh);
            }
        }

        // fold with x: col = nc*64 + n8*8 + c2 (+1); i = col/DOUT; o = col%DOUT
#pragma unroll
        for (int n8 = 0; n8 < 8; n8++) {
            int col0 = nc * 64 + n8 * 8 + c2;
            int i = col0 / DOUT;
            int os = col0 % DOUT;
            int slot = 2 * (os >> 3);
            float xa = sx[i * 128 + rA];
            float xb = sx[i * 128 + rA + 8];
            msg[0][slot]     += xa * d[n8][0];
            msg[0][slot + 1] += xa * d[n8][1];
            msg[1][slot]     += xb * d[n8][2];
            msg[1][slot + 1] += xb * d[n8][3];
        }
        __syncthreads();   // all warps done with buf before it's re-filled
    }

    // ---- scatter: one atomic per (edge, o); add per-node x@b2 term ----
#pragma unroll
    for (int p = 0; p < 2; p++) {
        int ge = e0 + rA + p * 8;
        if (ge < KE) {
            int sv = src[ge], dv = dst[ge];
            const float* tn = tnode + (long long)sv * DOUT;
            float* ap = agg + (long long)dv * DOUT;
#pragma unroll
            for (int s = 0; s < NSL; s++) {
                int o = (s >> 1) * 8 + c2 + (s & 1);
                atomicAdd(ap + o, msg[p][s] + tn[o]);
            }
        }
    }
}

// ---------------- node epilogue: mean + root GEMM + bias (+relu) ----------------
template <int DIN, int DOUT, bool MEAN, bool RELU>
__global__ __launch_bounds__(256)
void node_kernel(const float* __restrict__ xin, const float* __restrict__ agg,
                 const float* __restrict__ root, const float* __restrict__ bias,
                 const int* __restrict__ deg, float* __restrict__ out) {
    __shared__ float sroot[DIN * DOUT];
    __shared__ float sbias[DOUT];
    int tid = threadIdx.x;
    for (int i = tid; i < DIN * DOUT; i += 256) sroot[i] = root[i];
    if (tid < DOUT) sbias[tid] = bias[tid];
    __syncthreads();
    int idx = blockIdx.x * 256 + tid;
    if (idx >= KN * DOUT) return;
    int n = idx / DOUT, o = idx % DOUT;
    float v = agg[idx];
    if (MEAN) {
        int d = deg[n];
        v *= 1.f / (d > 0 ? (float)d : 1.f);
    }
    const float* xr = xin + n * DIN;
#pragma unroll
    for (int i = 0; i < DIN; i++) v = fmaf(xr[i], sroot[i * DOUT + o], v);
    v += sbias[o];
    if (RELU) v = fmaxf(v, 0.f);
    out[idx] = v;
}

// ---------------- launch ----------------
static constexpr int smem_mma(int DIN) {
    // A hi/lo + 2 B chunk buffers + sx
    return 2 * (128 * PK * 2) + 2 * (2 * 64 * PK * 2) + DIN * 128 * 4;
}

extern "C" void kernel_launch(void* const* d_in, const int* in_sizes, int n_in,
                              void* d_out, int out_size) {
    const float* x = (const float*)d_in[0];
    const int* ei = (const int*)d_in[1];  // int32 (JAX x64-disabled downcast)
    const float* ea = (const float*)d_in[2];
    auto f = [&](int i) { return (const float*)d_in[i]; };
    float* out = (float*)d_out;
    const int* src = ei;
    const int* dstp = ei + KE;

    void *agg_p, *deg_p, *h1_p, *h2_p, *t_p, *wc1, *wc2, *wmu, *wlv;
    cudaGetSymbolAddress(&agg_p, g_agg);
    cudaGetSymbolAddress(&deg_p, g_deg);
    cudaGetSymbolAddress(&h1_p, g_h1);
    cudaGetSymbolAddress(&h2_p, g_h2);
    cudaGetSymbolAddress(&t_p, g_t);
    cudaGetSymbolAddress(&wc1, g_w2t_c1);
    cudaGetSymbolAddress(&wc2, g_w2t_c2);
    cudaGetSymbolAddress(&wmu, g_w2t_mu);
    cudaGetSymbolAddress(&wlv, g_w2t_lv);

    cudaFuncSetAttribute(edge_mma_kernel<16, 32>,
                         cudaFuncAttributeMaxDynamicSharedMemorySize, smem_mma(16));
    cudaFuncSetAttribute(edge_mma_kernel<32, 32>,
                         cudaFuncAttributeMaxDynamicSharedMemorySize, smem_mma(32));
    cudaFuncSetAttribute(edge_mma_kernel<32, 16>,
                         cudaFuncAttributeMaxDynamicSharedMemorySize, smem_mma(32));

    const int TB = (KE + 127) / 128;
    const int ZB32 = (KN * 32 / 4 + 255) / 256;
    const int ZB16 = (KN * 16 / 4 + 255) / 256;
    const int NB32 = (KN * 32 + 255) / 256;
    const int NB16 = (KN * 16 + 255) / 256;

    // prep w2 images (in-graph, deterministic)
    prep_w2_kernel<<<(512 * 128 + 255) / 256, 256>>>(f(5), 512, (uint8_t*)wc1);
    prep_w2_kernel<<<(1024 * 128 + 255) / 256, 256>>>(f(11), 1024, (uint8_t*)wc2);
    prep_w2_kernel<<<(512 * 128 + 255) / 256, 256>>>(f(17), 512, (uint8_t*)wmu);
    prep_w2_kernel<<<(512 * 128 + 255) / 256, 256>>>(f(23), 512, (uint8_t*)wlv);

    zero_i_kernel<<<(KN + 255) / 256, 256>>>((int*)deg_p, KN);
    deg_kernel<<<(KE + 255) / 256, 256>>>(dstp);

    // conv1: 16 -> 32, mean, relu
    zero_f_kernel<<<ZB32, 256>>>((float*)agg_p, KN * 32);
    xb2_kernel<16, 32><<<NB32, 256>>>(x, f(6), (float*)t_p);
    edge_mma_kernel<16, 32><<<TB, 256, smem_mma(16)>>>(
        x, ea, src, dstp, f(3), f(4), (const uint8_t*)wc1, (const float*)t_p,
        (float*)agg_p);
    node_kernel<16, 32, true, true><<<NB32, 256>>>(
        x, (const float*)agg_p, f(7), f(8), (const int*)deg_p, (float*)h1_p);

    // conv2: 32 -> 32, mean, relu
    zero_f_kernel<<<ZB32, 256>>>((float*)agg_p, KN * 32);
    xb2_kernel<32, 32><<<NB32, 256>>>((const float*)h1_p, f(12), (float*)t_p);
    edge_mma_kernel<32, 32><<<TB, 256, smem_mma(32)>>>(
        (const float*)h1_p, ea, src, dstp, f(9), f(10), (const uint8_t*)wc2,
        (const float*)t_p, (float*)agg_p);
    node_kernel<32, 32, true, true><<<NB32, 256>>>(
        (const float*)h1_p, (const float*)agg_p, f(13), f(14), (const int*)deg_p,
        (float*)h2_p);

    // mu: 32 -> 16, sum
    zero_f_kernel<<<ZB16, 256>>>((float*)agg_p, KN * 16);
    xb2_kernel<32, 16><<<NB16, 256>>>((const float*)h2_p, f(18), (float*)t_p);
    edge_mma_kernel<32, 16><<<TB, 256, smem_mma(32)>>>(
        (const float*)h2_p, ea, src, dstp, f(15), f(16), (const uint8_t*)wmu,
        (const float*)t_p, (float*)agg_p);
    node_kernel<32, 16, false, false><<<NB16, 256>>>(
        (const float*)h2_p, (const float*)agg_p, f(19), f(20), (const int*)deg_p,
        out);

    // logvar: 32 -> 16, sum
    zero_f_kernel<<<ZB16, 256>>>((float*)agg_p, KN * 16);
    xb2_kernel<32, 16><<<NB16, 256>>>((const float*)h2_p, f(24), (float*)t_p);
    edge_mma_kernel<32, 16><<<TB, 256, smem_mma(32)>>>(
        (const float*)h2_p, ea, src, dstp, f(21), f(22), (const uint8_t*)wlv,
        (const float*)t_p, (float*)agg_p);
    node_kernel<32, 16, false, false><<<NB16, 256>>>(
        (const float*)h2_p, (const float*)agg_p, f(25), f(26), (const int*)deg_p,
        out + KN * 16);
}